// round 15
// baseline (speedup 1.0000x reference)
#include <cuda_runtime.h>

#define MARGIN 1.0f
#define EPS 1e-6f

// Scratch (no device allocation). B=16384, 16 rows/block -> 1024 blocks.
__device__ float        g_partials[4096];
__device__ unsigned int g_ticket = 0;

// 8 warps/block, each warp processes TWO rows interleaved (6 load streams
// per loop body -> ~2x memory-level parallelism vs 1 row/warp).
__global__ void __launch_bounds__(256, 4)
hinge_fused2_kernel(const float* __restrict__ out,
                    const float* __restrict__ tgt,
                    const int* __restrict__ neg,     // int32 indices (JAX x64-off)
                    float* __restrict__ result,
                    int B, int D, int nblocks)
{
    __shared__ float sh[8];
    __shared__ bool  is_last;

    const int warp = threadIdx.x >> 5;
    const int lane = threadIdx.x & 31;
    const int r0   = (blockIdx.x * 8 + warp) * 2;   // first of the warp's 2 rows
    const int r1   = r0 + 1;

    float h01 = 0.f;  // sum of this warp's two hinge values (lane 0 only)

    if (r1 < B) {
        // Trap-proof wrap: unsigned modulo keeps j in [0, B) for ANY value.
        unsigned int j0 = ((unsigned int)(r0 + 1) + (unsigned int)neg[r0]) % (unsigned int)B;
        unsigned int j1 = ((unsigned int)(r1 + 1) + (unsigned int)neg[r1]) % (unsigned int)B;

        const float4* __restrict__ oa = (const float4*)(out + (size_t)r0 * D);
        const float4* __restrict__ ob = (const float4*)(out + (size_t)r1 * D);
        const float4* __restrict__ ta = (const float4*)(tgt + (size_t)r0 * D);
        const float4* __restrict__ tb = (const float4*)(tgt + (size_t)r1 * D);
        const float4* __restrict__ ga = (const float4*)(tgt + (size_t)j0 * D);
        const float4* __restrict__ gb = (const float4*)(tgt + (size_t)j1 * D);

        float dp0 = 0.f, dn0 = 0.f, no0 = 0.f, nt0 = 0.f, nn0 = 0.f;
        float dp1 = 0.f, dn1 = 0.f, no1 = 0.f, nt1 = 0.f, nn1 = 0.f;

        const int nv = D >> 2;   // 256 float4 per row; 8 iters per lane
        #pragma unroll 8
        for (int k = lane; k < nv; k += 32) {
            // Batch all 6 independent loads first (maximize in-flight lines).
            float4 o0 = __ldcs(&oa[k]);
            float4 o1 = __ldcs(&ob[k]);
            float4 t0 = ta[k];
            float4 t1 = tb[k];
            float4 g0 = ga[k];
            float4 g1 = gb[k];

            dp0 += o0.x*t0.x + o0.y*t0.y + o0.z*t0.z + o0.w*t0.w;
            dn0 += o0.x*g0.x + o0.y*g0.y + o0.z*g0.z + o0.w*g0.w;
            no0 += o0.x*o0.x + o0.y*o0.y + o0.z*o0.z + o0.w*o0.w;
            nt0 += t0.x*t0.x + t0.y*t0.y + t0.z*t0.z + t0.w*t0.w;
            nn0 += g0.x*g0.x + g0.y*g0.y + g0.z*g0.z + g0.w*g0.w;

            dp1 += o1.x*t1.x + o1.y*t1.y + o1.z*t1.z + o1.w*t1.w;
            dn1 += o1.x*g1.x + o1.y*g1.y + o1.z*g1.z + o1.w*g1.w;
            no1 += o1.x*o1.x + o1.y*o1.y + o1.z*o1.z + o1.w*o1.w;
            nt1 += t1.x*t1.x + t1.y*t1.y + t1.z*t1.z + t1.w*t1.w;
            nn1 += g1.x*g1.x + g1.y*g1.y + g1.z*g1.z + g1.w*g1.w;
        }

        #pragma unroll
        for (int off = 16; off > 0; off >>= 1) {
            dp0 += __shfl_xor_sync(0xFFFFFFFFu, dp0, off);
            dn0 += __shfl_xor_sync(0xFFFFFFFFu, dn0, off);
            no0 += __shfl_xor_sync(0xFFFFFFFFu, no0, off);
            nt0 += __shfl_xor_sync(0xFFFFFFFFu, nt0, off);
            nn0 += __shfl_xor_sync(0xFFFFFFFFu, nn0, off);
            dp1 += __shfl_xor_sync(0xFFFFFFFFu, dp1, off);
            dn1 += __shfl_xor_sync(0xFFFFFFFFu, dn1, off);
            no1 += __shfl_xor_sync(0xFFFFFFFFu, no1, off);
            nt1 += __shfl_xor_sync(0xFFFFFFFFu, nt1, off);
            nn1 += __shfl_xor_sync(0xFFFFFFFFu, nn1, off);
        }

        if (lane == 0) {
            float s0 = sqrtf(no0);
            float h0 = fmaxf(0.f, MARGIN - dp0 / fmaxf(sqrtf(nt0) * s0, EPS)
                                         + dn0 / fmaxf(sqrtf(nn0) * s0, EPS));
            float s1 = sqrtf(no1);
            float h1 = fmaxf(0.f, MARGIN - dp1 / fmaxf(sqrtf(nt1) * s1, EPS)
                                         + dn1 / fmaxf(sqrtf(nn1) * s1, EPS));
            h01 = h0 + h1;   // fixed order
        }
    }

    if (lane == 0) sh[warp] = h01;
    __syncthreads();

    // Thread 0: fixed-order block sum, publish, take ticket.
    if (threadIdx.x == 0) {
        float bs = 0.f;
        #pragma unroll
        for (int w = 0; w < 8; w++) bs += sh[w];
        g_partials[blockIdx.x] = bs;
        __threadfence();
        unsigned int t = atomicAdd(&g_ticket, 1u);
        is_last = (t == (unsigned int)(nblocks - 1));
    }
    __syncthreads();

    if (!is_last) return;

    // Last block: deterministic fixed-order reduction of block partials.
    float s = 0.f;
    for (int k = threadIdx.x; k < nblocks; k += blockDim.x) s += g_partials[k];

    #pragma unroll
    for (int off = 16; off > 0; off >>= 1)
        s += __shfl_xor_sync(0xFFFFFFFFu, s, off);

    if (lane == 0) sh[warp] = s;
    __syncthreads();

    if (threadIdx.x == 0) {
        float tot = 0.f;
        #pragma unroll
        for (int w = 0; w < 8; w++) tot += sh[w];
        result[0] = tot / (float)B;
        g_ticket = 0;   // reset for next graph replay
    }
}

extern "C" void kernel_launch(void* const* d_in, const int* in_sizes, int n_in,
                              void* d_out, int out_size)
{
    const float* out = (const float*)d_in[0];   // output [B, D] f32
    const float* tgt = (const float*)d_in[1];   // target [B, D] f32
    const int*   neg = (const int*)d_in[2];     // neg_idx [B] int32

    const int B = in_sizes[2];
    const int D = in_sizes[0] / B;

    const int threads = 256;                 // 8 warps, 2 rows each = 16 rows/block
    const int grid = (B + 15) / 16;          // 1024 blocks for B=16384

    hinge_fused2_kernel<<<grid, threads>>>(out, tgt, neg, (float*)d_out, B, D, grid);
}

// round 16
// speedup vs baseline: 1.0387x; 1.0387x over previous
#include <cuda_runtime.h>

#define MARGIN 1.0f
#define EPS 1e-6f

// Scratch (no device allocation allowed).
__device__ float        g_partials[4096];
__device__ unsigned int g_ticket = 0;

// Persistent warp-per-row kernel with explicit next-iteration prefetch.
// 8 warps/block, grid sized to exactly fill the chip at occupancy 5.
__global__ void __launch_bounds__(256, 5)
hinge_persist_kernel(const float* __restrict__ out,
                     const float* __restrict__ tgt,
                     const int* __restrict__ neg,    // int32 indices
                     float* __restrict__ result,
                     int B, int D, int nblocks)
{
    __shared__ float sh[8];
    __shared__ bool  is_last;

    const int warp    = threadIdx.x >> 5;
    const int lane    = threadIdx.x & 31;
    const int gwarp   = blockIdx.x * 8 + warp;
    const int wstride = nblocks * 8;
    const int iters   = D >> 7;   // float4s per lane per row (D=1024 -> 8)

    float hsum = 0.f;   // fixed-order per-warp accumulation over its rows

    for (int row = gwarp; row < B; row += wstride) {
        unsigned int j = ((unsigned int)(row + 1) + (unsigned int)neg[row])
                         % (unsigned int)B;

        const float4* __restrict__ o4 = (const float4*)(out + (size_t)row * D) + lane;
        const float4* __restrict__ t4 = (const float4*)(tgt + (size_t)row * D) + lane;
        const float4* __restrict__ g4 = (const float4*)(tgt + (size_t)j   * D) + lane;

        float dp = 0.f, dn = 0.f, no = 0.f, nt = 0.f, nn = 0.f;

        // Prefetch iteration 0.
        float4 o_c = __ldcs(o4);
        float4 t_c = *t4;
        float4 g_c = *g4;

        #pragma unroll 8
        for (int k = 1; k <= iters; k++) {
            float4 o_n, t_n, g_n;
            if (k < iters) {                 // issue NEXT loads before FMAs
                o_n = __ldcs(o4 + k * 32);
                t_n = *(t4 + k * 32);
                g_n = *(g4 + k * 32);
            }
            dp += o_c.x*t_c.x + o_c.y*t_c.y + o_c.z*t_c.z + o_c.w*t_c.w;
            dn += o_c.x*g_c.x + o_c.y*g_c.y + o_c.z*g_c.z + o_c.w*g_c.w;
            no += o_c.x*o_c.x + o_c.y*o_c.y + o_c.z*o_c.z + o_c.w*o_c.w;
            nt += t_c.x*t_c.x + t_c.y*t_c.y + t_c.z*t_c.z + t_c.w*t_c.w;
            nn += g_c.x*g_c.x + g_c.y*g_c.y + g_c.z*g_c.z + g_c.w*g_c.w;
            o_c = o_n; t_c = t_n; g_c = g_n;
        }

        #pragma unroll
        for (int off = 16; off > 0; off >>= 1) {
            dp += __shfl_xor_sync(0xFFFFFFFFu, dp, off);
            dn += __shfl_xor_sync(0xFFFFFFFFu, dn, off);
            no += __shfl_xor_sync(0xFFFFFFFFu, no, off);
            nt += __shfl_xor_sync(0xFFFFFFFFu, nt, off);
            nn += __shfl_xor_sync(0xFFFFFFFFu, nn, off);
        }

        if (lane == 0) {
            float s = sqrtf(no);
            hsum += fmaxf(0.f, MARGIN - dp / fmaxf(sqrtf(nt) * s, EPS)
                                      + dn / fmaxf(sqrtf(nn) * s, EPS));
        }
    }

    if (lane == 0) sh[warp] = hsum;
    __syncthreads();

    // Thread 0: fixed-order block sum, publish, take ticket.
    if (threadIdx.x == 0) {
        float bs = 0.f;
        #pragma unroll
        for (int w = 0; w < 8; w++) bs += sh[w];
        g_partials[blockIdx.x] = bs;
        __threadfence();
        unsigned int t = atomicAdd(&g_ticket, 1u);
        is_last = (t == (unsigned int)(nblocks - 1));
    }
    __syncthreads();

    if (!is_last) return;

    // Last block: deterministic fixed-order reduction of block partials.
    float s = 0.f;
    for (int k = threadIdx.x; k < nblocks; k += blockDim.x) s += g_partials[k];

    #pragma unroll
    for (int off = 16; off > 0; off >>= 1)
        s += __shfl_xor_sync(0xFFFFFFFFu, s, off);

    if (lane == 0) sh[warp] = s;
    __syncthreads();

    if (threadIdx.x == 0) {
        float tot = 0.f;
        #pragma unroll
        for (int w = 0; w < 8; w++) tot += sh[w];
        result[0] = tot / (float)B;
        g_ticket = 0;   // reset for next graph replay
    }
}

extern "C" void kernel_launch(void* const* d_in, const int* in_sizes, int n_in,
                              void* d_out, int out_size)
{
    const float* out = (const float*)d_in[0];   // output [B, D] f32
    const float* tgt = (const float*)d_in[1];   // target [B, D] f32
    const int*   neg = (const int*)d_in[2];     // neg_idx [B] int32

    const int B = in_sizes[2];
    const int D = in_sizes[0] / B;

    const int threads = 256;                          // 8 warps/block
    int grid = 148 * 5;                               // exact fill at occ=5
    const int max_grid = (B + 7) / 8;                 // never more blocks than rows
    if (grid > max_grid) grid = max_grid;

    hinge_persist_kernel<<<grid, threads>>>(out, tgt, neg, (float*)d_out, B, D, grid);
}

// round 17
// speedup vs baseline: 1.3385x; 1.2886x over previous
#include <cuda_runtime.h>

#define MARGIN 1.0f
#define EPS 1e-6f

// Scratch (no device allocation allowed).
__device__ float        g_partials[4096];
__device__ unsigned int g_ticket = 0;

// ---------------------------------------------------------------------------
// Specialized fast path: D known at compile time, B a power of two.
// Persistent warp-per-row with (a) fully resolved unroll (no runtime
// predication), (b) mask instead of modulo, (c) ROW-LEVEL software pipeline:
// the last unrolled iteration prefetches the NEXT row's first loads, so the
// warp keeps ~1.5KB in flight underneath the shuffle reduction + hinge math.
// ---------------------------------------------------------------------------
template<int DCONST>
__global__ void __launch_bounds__(256, 5)
hinge_pipe_kernel(const float* __restrict__ out,
                  const float* __restrict__ tgt,
                  const int* __restrict__ neg,
                  float* __restrict__ result,
                  int B, unsigned int Bmask, int nblocks)
{
    __shared__ float sh[8];
    __shared__ bool  is_last;

    constexpr int ITERS = DCONST / 128;   // float4s per lane per row (D=1024 -> 8)

    const int warp    = threadIdx.x >> 5;
    const int lane    = threadIdx.x & 31;
    const int wstride = nblocks * 8;

    float hsum = 0.f;

    int  row   = blockIdx.x * 8 + warp;
    bool valid = row < B;

    const float4* o4 = nullptr;
    const float4* t4 = nullptr;
    const float4* g4 = nullptr;
    float4 o_c, t_c, g_c;

    if (valid) {
        unsigned int j = ((unsigned int)(row + 1) + (unsigned int)neg[row]) & Bmask;
        o4 = (const float4*)(out + (size_t)row * DCONST) + lane;
        t4 = (const float4*)(tgt + (size_t)row * DCONST) + lane;
        g4 = (const float4*)(tgt + (size_t)j   * DCONST) + lane;
        o_c = __ldcs(o4);
        t_c = *t4;
        g_c = *g4;
    }

    while (valid) {
        const int  nrow   = row + wstride;
        const bool nvalid = nrow < B;

        float dp = 0.f, dn = 0.f, no = 0.f, nt = 0.f, nn = 0.f;

        #pragma unroll
        for (int k = 1; k <= ITERS; k++) {
            float4 o_n, t_n, g_n;
            if (k < ITERS) {
                // compile-time branch: bare loads with immediate offsets
                o_n = __ldcs(o4 + k * 32);
                t_n = *(t4 + k * 32);
                g_n = *(g4 + k * 32);
            } else if (nvalid) {
                // last body: prefetch NEXT ROW's iteration 0 (stays in flight
                // through the reduction below)
                unsigned int j2 = ((unsigned int)(nrow + 1) + (unsigned int)neg[nrow]) & Bmask;
                o4 = (const float4*)(out + (size_t)nrow * DCONST) + lane;
                t4 = (const float4*)(tgt + (size_t)nrow * DCONST) + lane;
                g4 = (const float4*)(tgt + (size_t)j2   * DCONST) + lane;
                o_n = __ldcs(o4);
                t_n = *t4;
                g_n = *g4;
            }

            dp += o_c.x*t_c.x + o_c.y*t_c.y + o_c.z*t_c.z + o_c.w*t_c.w;
            dn += o_c.x*g_c.x + o_c.y*g_c.y + o_c.z*g_c.z + o_c.w*g_c.w;
            no += o_c.x*o_c.x + o_c.y*o_c.y + o_c.z*o_c.z + o_c.w*o_c.w;
            nt += t_c.x*t_c.x + t_c.y*t_c.y + t_c.z*t_c.z + t_c.w*t_c.w;
            nn += g_c.x*g_c.x + g_c.y*g_c.y + g_c.z*g_c.z + g_c.w*g_c.w;

            o_c = o_n; t_c = t_n; g_c = g_n;
        }

        #pragma unroll
        for (int off = 16; off > 0; off >>= 1) {
            dp += __shfl_xor_sync(0xFFFFFFFFu, dp, off);
            dn += __shfl_xor_sync(0xFFFFFFFFu, dn, off);
            no += __shfl_xor_sync(0xFFFFFFFFu, no, off);
            nt += __shfl_xor_sync(0xFFFFFFFFu, nt, off);
            nn += __shfl_xor_sync(0xFFFFFFFFu, nn, off);
        }

        if (lane == 0) {
            float s = sqrtf(no);
            hsum += fmaxf(0.f, MARGIN - dp / fmaxf(sqrtf(nt) * s, EPS)
                                      + dn / fmaxf(sqrtf(nn) * s, EPS));
        }

        row = nrow; valid = nvalid;
    }

    if (lane == 0) sh[warp] = hsum;
    __syncthreads();

    if (threadIdx.x == 0) {
        float bs = 0.f;
        #pragma unroll
        for (int w = 0; w < 8; w++) bs += sh[w];
        g_partials[blockIdx.x] = bs;
        __threadfence();
        unsigned int t = atomicAdd(&g_ticket, 1u);
        is_last = (t == (unsigned int)(nblocks - 1));
    }
    __syncthreads();

    if (!is_last) return;

    float s = 0.f;
    for (int k = threadIdx.x; k < nblocks; k += blockDim.x) s += g_partials[k];
    #pragma unroll
    for (int off = 16; off > 0; off >>= 1)
        s += __shfl_xor_sync(0xFFFFFFFFu, s, off);
    if (lane == 0) sh[warp] = s;
    __syncthreads();
    if (threadIdx.x == 0) {
        float tot = 0.f;
        #pragma unroll
        for (int w = 0; w < 8; w++) tot += sh[w];
        result[0] = tot / (float)B;
        g_ticket = 0;
    }
}

// ---------------------------------------------------------------------------
// Generic fallback (R15 kernel): runtime D, arbitrary B.
// ---------------------------------------------------------------------------
__global__ void __launch_bounds__(256, 5)
hinge_generic_kernel(const float* __restrict__ out,
                     const float* __restrict__ tgt,
                     const int* __restrict__ neg,
                     float* __restrict__ result,
                     int B, int D, int nblocks)
{
    __shared__ float sh[8];
    __shared__ bool  is_last;

    const int warp    = threadIdx.x >> 5;
    const int lane    = threadIdx.x & 31;
    const int gwarp   = blockIdx.x * 8 + warp;
    const int wstride = nblocks * 8;
    const int nv      = D >> 2;

    float hsum = 0.f;

    for (int row = gwarp; row < B; row += wstride) {
        unsigned int j = ((unsigned int)(row + 1) + (unsigned int)neg[row])
                         % (unsigned int)B;
        const float4* o4 = (const float4*)(out + (size_t)row * D);
        const float4* t4 = (const float4*)(tgt + (size_t)row * D);
        const float4* g4 = (const float4*)(tgt + (size_t)j   * D);

        float dp = 0.f, dn = 0.f, no = 0.f, nt = 0.f, nn = 0.f;
        for (int k = lane; k < nv; k += 32) {
            float4 o = __ldcs(&o4[k]);
            float4 t = t4[k];
            float4 g = g4[k];
            dp += o.x*t.x + o.y*t.y + o.z*t.z + o.w*t.w;
            dn += o.x*g.x + o.y*g.y + o.z*g.z + o.w*g.w;
            no += o.x*o.x + o.y*o.y + o.z*o.z + o.w*o.w;
            nt += t.x*t.x + t.y*t.y + t.z*t.z + t.w*t.w;
            nn += g.x*g.x + g.y*g.y + g.z*g.z + g.w*g.w;
        }
        #pragma unroll
        for (int off = 16; off > 0; off >>= 1) {
            dp += __shfl_xor_sync(0xFFFFFFFFu, dp, off);
            dn += __shfl_xor_sync(0xFFFFFFFFu, dn, off);
            no += __shfl_xor_sync(0xFFFFFFFFu, no, off);
            nt += __shfl_xor_sync(0xFFFFFFFFu, nt, off);
            nn += __shfl_xor_sync(0xFFFFFFFFu, nn, off);
        }
        if (lane == 0) {
            float s = sqrtf(no);
            hsum += fmaxf(0.f, MARGIN - dp / fmaxf(sqrtf(nt) * s, EPS)
                                      + dn / fmaxf(sqrtf(nn) * s, EPS));
        }
    }

    if (lane == 0) sh[warp] = hsum;
    __syncthreads();
    if (threadIdx.x == 0) {
        float bs = 0.f;
        #pragma unroll
        for (int w = 0; w < 8; w++) bs += sh[w];
        g_partials[blockIdx.x] = bs;
        __threadfence();
        unsigned int t = atomicAdd(&g_ticket, 1u);
        is_last = (t == (unsigned int)(nblocks - 1));
    }
    __syncthreads();
    if (!is_last) return;

    float s = 0.f;
    for (int k = threadIdx.x; k < nblocks; k += blockDim.x) s += g_partials[k];
    #pragma unroll
    for (int off = 16; off > 0; off >>= 1)
        s += __shfl_xor_sync(0xFFFFFFFFu, s, off);
    if (lane == 0) sh[warp] = s;
    __syncthreads();
    if (threadIdx.x == 0) {
        float tot = 0.f;
        #pragma unroll
        for (int w = 0; w < 8; w++) tot += sh[w];
        result[0] = tot / (float)B;
        g_ticket = 0;
    }
}

extern "C" void kernel_launch(void* const* d_in, const int* in_sizes, int n_in,
                              void* d_out, int out_size)
{
    const float* out = (const float*)d_in[0];   // output [B, D] f32
    const float* tgt = (const float*)d_in[1];   // target [B, D] f32
    const int*   neg = (const int*)d_in[2];     // neg_idx [B] int32

    const int B = in_sizes[2];
    const int D = in_sizes[0] / B;

    const int threads = 256;
    int grid = 148 * 5;                         // exact fill at occ=5
    const int max_grid = (B + 7) / 8;
    if (grid > max_grid) grid = max_grid;

    const bool b_pow2 = (B & (B - 1)) == 0;

    if (D == 1024 && b_pow2) {
        hinge_pipe_kernel<1024><<<grid, threads>>>(out, tgt, neg, (float*)d_out,
                                                   B, (unsigned int)(B - 1), grid);
    } else {
        hinge_generic_kernel<<<grid, threads>>>(out, tgt, neg, (float*)d_out,
                                                B, D, grid);
    }
}